// round 2
// baseline (speedup 1.0000x reference)
#include <cuda_runtime.h>
#include <math.h>

#define BATCH 8
#define DIM   128
#define NSEQ  2048
#define BM    64          // m-tile (K/output columns) per block
#define BN    64          // n-tile (Q columns / reduction dim of PV)
#define LDS_  68          // padded smem leading dim (floats), multiple of 4

// smem: Ks[128][68] + Qc[32][68] + Vs[128][68] + Ps[64][68]
#define SMEM_FLOATS ((DIM + 32 + DIM + BN) * LDS_)
#define SMEM_BYTES  (SMEM_FLOATS * 4)

__global__ __launch_bounds__(256, 2)
void sigattn_kernel(const float* __restrict__ Q, const float* __restrict__ K,
                    const float* __restrict__ V, float* __restrict__ O) {
    extern __shared__ float sm[];
    float* Ks = sm;                     // [128][LDS_]  K tile, resident whole block
    float* Qc = Ks + DIM * LDS_;        // [32][LDS_]   Q d-chunk
    float* Vs = Qc + 32  * LDS_;        // [128][LDS_]  V tile
    float* Ps = Vs + DIM * LDS_;        // [64][LDS_]   sigmoid scores

    const int b  = blockIdx.y;
    const int m0 = blockIdx.x * BM;
    const float* Qb = Q + (size_t)b * DIM * NSEQ;
    const float* Kb = K + (size_t)b * DIM * NSEQ;
    const float* Vb = V + (size_t)b * DIM * NSEQ;
    float*       Ob = O + (size_t)b * DIM * NSEQ;

    const int tid = threadIdx.x;
    const int tm  = tid & 15;   // 0..15 : m microtile index
    const int tn  = tid >> 4;   // 0..15 : n microtile (phase1) / v microtile (phase2)

    // ---- Load K tile once: Ks[d][j] = K[b][d][m0+j] ----
    for (int i = tid; i < DIM * (BM / 4); i += 256) {
        int d  = i >> 4;            // BM/4 = 16 float4 per row
        int j4 = (i & 15) << 2;
        float4 v = *(const float4*)(Kb + (size_t)d * NSEQ + m0 + j4);
        *(float4*)(&Ks[d * LDS_ + j4]) = v;
    }

    float acc[8][4];
#pragma unroll
    for (int i = 0; i < 8; i++)
#pragma unroll
        for (int j = 0; j < 4; j++) acc[i][j] = 0.0f;

    const float scale = 0.08838834764831845f;  // 1/sqrt(128)

    for (int n0 = 0; n0 < NSEQ; n0 += BN) {
        // ---------- Phase 1: S[n,m] = sum_d Q[d,n]*K[d,m] ----------
        float s[4][4];
#pragma unroll
        for (int i = 0; i < 4; i++)
#pragma unroll
            for (int j = 0; j < 4; j++) s[i][j] = 0.0f;

        for (int dc = 0; dc < DIM; dc += 32) {
            __syncthreads();  // protect Qc reuse (and phase-2 reads of prev iter)
            for (int i = tid; i < 32 * 16; i += 256) {
                int dr = i >> 4;
                int j4 = (i & 15) << 2;
                *(float4*)(&Qc[dr * LDS_ + j4]) =
                    *(const float4*)(Qb + (size_t)(dc + dr) * NSEQ + n0 + j4);
            }
            __syncthreads();
#pragma unroll 8
            for (int d = 0; d < 32; d++) {
                float4 q = *(const float4*)(&Qc[d * LDS_ + tn * 4]);
                float4 k = *(const float4*)(&Ks[(dc + d) * LDS_ + tm * 4]);
                s[0][0] += q.x * k.x; s[0][1] += q.x * k.y; s[0][2] += q.x * k.z; s[0][3] += q.x * k.w;
                s[1][0] += q.y * k.x; s[1][1] += q.y * k.y; s[1][2] += q.y * k.z; s[1][3] += q.y * k.w;
                s[2][0] += q.z * k.x; s[2][1] += q.z * k.y; s[2][2] += q.z * k.z; s[2][3] += q.z * k.w;
                s[3][0] += q.w * k.x; s[3][1] += q.w * k.y; s[3][2] += q.w * k.z; s[3][3] += q.w * k.w;
            }
        }

        // ---------- sigmoid -> Ps, stream V tile ----------
#pragma unroll
        for (int i = 0; i < 4; i++) {
            float4 p;
            p.x = 1.0f / (1.0f + __expf(-s[i][0] * scale));
            p.y = 1.0f / (1.0f + __expf(-s[i][1] * scale));
            p.z = 1.0f / (1.0f + __expf(-s[i][2] * scale));
            p.w = 1.0f / (1.0f + __expf(-s[i][3] * scale));
            *(float4*)(&Ps[(tn * 4 + i) * LDS_ + tm * 4]) = p;
        }
        for (int i = tid; i < DIM * 16; i += 256) {
            int v  = i >> 4;
            int j4 = (i & 15) << 2;
            *(float4*)(&Vs[v * LDS_ + j4]) =
                *(const float4*)(Vb + (size_t)v * NSEQ + n0 + j4);
        }
        __syncthreads();

        // ---------- Phase 2: O[v,m] += sum_n V[v,n]*P[n,m] ----------
#pragma unroll 2
        for (int nn = 0; nn < BN; nn += 4) {
            float4 p0 = *(const float4*)(&Ps[(nn + 0) * LDS_ + tm * 4]);
            float4 p1 = *(const float4*)(&Ps[(nn + 1) * LDS_ + tm * 4]);
            float4 p2 = *(const float4*)(&Ps[(nn + 2) * LDS_ + tm * 4]);
            float4 p3 = *(const float4*)(&Ps[(nn + 3) * LDS_ + tm * 4]);
#pragma unroll
            for (int i = 0; i < 8; i++) {
                float4 va = *(const float4*)(&Vs[(tn * 8 + i) * LDS_ + nn]);
                acc[i][0] += va.x * p0.x + va.y * p1.x + va.z * p2.x + va.w * p3.x;
                acc[i][1] += va.x * p0.y + va.y * p1.y + va.z * p2.y + va.w * p3.y;
                acc[i][2] += va.x * p0.z + va.y * p1.z + va.z * p2.z + va.w * p3.z;
                acc[i][3] += va.x * p0.w + va.y * p1.w + va.z * p2.w + va.w * p3.w;
            }
        }
    }

    // ---- Write O[v][m0+..] ----
#pragma unroll
    for (int i = 0; i < 8; i++) {
        float4 o;
        o.x = acc[i][0]; o.y = acc[i][1]; o.z = acc[i][2]; o.w = acc[i][3];
        *(float4*)(Ob + (size_t)(tn * 8 + i) * NSEQ + m0 + tm * 4) = o;
    }
}

extern "C" void kernel_launch(void* const* d_in, const int* in_sizes, int n_in,
                              void* d_out, int out_size) {
    const float* Q = (const float*)d_in[0];
    const float* K = (const float*)d_in[1];
    const float* V = (const float*)d_in[2];
    float* O = (float*)d_out;

    cudaFuncSetAttribute(sigattn_kernel,
                         cudaFuncAttributeMaxDynamicSharedMemorySize, SMEM_BYTES);

    dim3 grid(NSEQ / BM, BATCH);
    sigattn_kernel<<<grid, 256, SMEM_BYTES>>>(Q, K, V, O);
}

// round 4
// speedup vs baseline: 7.8445x; 7.8445x over previous
#include <cuda_runtime.h>
#include <cuda_fp16.h>
#include <cstdint>

#define B_ 8
#define D_ 128
#define N_ 2048
#define BN 64
#define NITER (N_ / BN)

__device__ __align__(16) __half g_Qt[B_ * N_ * D_];  // [b][n][d]
__device__ __align__(16) __half g_Kt[B_ * N_ * D_];  // [b][m][d]
__device__ __align__(16) __half g_Vh[B_ * D_ * N_];  // [b][v][n]

__device__ __forceinline__ uint32_t s2u(const void* p) {
    uint32_t a;
    asm("{ .reg .u64 t; cvta.to.shared.u64 t, %1; cvt.u32.u64 %0, t; }" : "=r"(a) : "l"(p));
    return a;
}

#define CPA16(dst, src) \
    asm volatile("cp.async.cg.shared.global [%0], [%1], 16;" :: "r"(dst), "l"(src))
#define CPA_COMMIT() asm volatile("cp.async.commit_group;" ::: "memory")
#define CPA_WAIT0()  asm volatile("cp.async.wait_group 0;" ::: "memory")

__device__ __forceinline__ void ldmx4(uint32_t* r, uint32_t addr) {
    asm volatile("ldmatrix.sync.aligned.m8n8.x4.shared.b16 {%0,%1,%2,%3}, [%4];"
        : "=r"(r[0]), "=r"(r[1]), "=r"(r[2]), "=r"(r[3]) : "r"(addr));
}
__device__ __forceinline__ void mma16816(float* d, const uint32_t* a, const uint32_t* b) {
    asm volatile("mma.sync.aligned.m16n8k16.row.col.f32.f16.f16.f32 "
        "{%0,%1,%2,%3}, {%4,%5,%6,%7}, {%8,%9}, {%0,%1,%2,%3};"
        : "+f"(d[0]), "+f"(d[1]), "+f"(d[2]), "+f"(d[3])
        : "r"(a[0]), "r"(a[1]), "r"(a[2]), "r"(a[3]), "r"(b[0]), "r"(b[1]));
}

// sigmoid(x / sqrt(128)) via ex2.approx + rcp.approx
__device__ __forceinline__ float sigf(float x) {
    const float c1 = (float)(-0.08838834764831845 * 1.4426950408889634);
    float t, r;
    asm("ex2.approx.f32 %0, %1;" : "=f"(t) : "f"(x * c1));
    asm("rcp.approx.f32 %0, %1;" : "=f"(r) : "f"(1.0f + t));
    return r;
}
__device__ __forceinline__ uint32_t packh2(float a, float b) {
    uint32_t r;
    asm("cvt.rn.f16x2.f32 %0, %1, %2;" : "=r"(r) : "f"(b), "f"(a));
    return r;
}

// smem: K tile 32KB @0, Q[buf] 16KB @32K+buf*16K, V[buf] 16KB @64K+buf*16K
#define SM_K 0
#define SM_Q 32768
#define SM_V 65536
#define SMEM_TOTAL 98304

__global__ __launch_bounds__(256, 1)
void sigattn_hmma(float* __restrict__ O) {
    extern __shared__ char sm[];
    const uint32_t sb = s2u(sm);
    const int tid = threadIdx.x, w = tid >> 5, lane = tid & 31;
    const int b = blockIdx.y, m0 = blockIdx.x * 128;

    // ---- loaders (cp.async, XOR-swizzled 16B chunks) ----
    auto loadQV = [&](int it, int buf) {
        const int n0 = it * BN;
        const uint32_t qd = sb + SM_Q + buf * 16384;
        const uint32_t vd = sb + SM_V + buf * 16384;
#pragma unroll
        for (int r = 0; r < 4; r++) {
            int i = tid + r * 256;
            int n = i >> 4, c = i & 15;          // Q: 64 rows x 16 chunks
            CPA16(qd + n * 256 + ((c ^ (n & 7)) << 4),
                  (const char*)g_Qt + ((size_t)(b * N_ + n0 + n) * 128 + c * 8) * 2);
            int v = i >> 3, cv = i & 7;          // V: 128 rows x 8 chunks
            CPA16(vd + v * 128 + ((cv ^ (v & 7)) << 4),
                  (const char*)g_Vh + ((size_t)(b * D_ + v) * N_ + n0 + cv * 8) * 2);
        }
    };

    // prologue: K tile + (Q,V)(0)
#pragma unroll
    for (int r = 0; r < 8; r++) {
        int i = tid + r * 256;
        int m = i >> 4, c = i & 15;
        CPA16(sb + SM_K + m * 256 + ((c ^ (m & 7)) << 4),
              (const char*)g_Kt + ((size_t)(b * N_ + m0 + m) * 128 + c * 8) * 2);
    }
    loadQV(0, 0);
    CPA_COMMIT();
    CPA_WAIT0();
    __syncthreads();

    // ---- K warp-tile -> registers (resident) ----
    uint32_t kf[8][4];
    {
        const uint32_t kbase = sb + SM_K + (w * 16 + (lane & 15)) * 256;
#pragma unroll
        for (int kc = 0; kc < 8; kc++)
            ldmx4(kf[kc], kbase + (((2 * kc + (lane >> 4)) ^ (lane & 7)) << 4));
    }

    float ob[16][4];
#pragma unroll
    for (int i = 0; i < 16; i++)
#pragma unroll
        for (int j = 0; j < 4; j++) ob[i][j] = 0.0f;

    const int rL  = (lane & 7) + ((lane >> 4) << 3);  // ldmatrix row-in-16 for this lane
    const int cp_ = (lane >> 3) & 1;                  // chunk parity
    const int sx  = lane & 7;                         // swizzle key

    for (int it = 0; it < NITER; it++) {
        const int buf = it & 1;
        if (it + 1 < NITER) { loadQV(it + 1, buf ^ 1); }
        CPA_COMMIT();

        // ---- MMA1: S'[16 m, 64 n] = K . Q^T ----
        float sc[8][4];
#pragma unroll
        for (int j = 0; j < 8; j++)
#pragma unroll
            for (int q = 0; q < 4; q++) sc[j][q] = 0.0f;

        const uint32_t qbase = sb + SM_Q + buf * 16384 + rL * 256;
#pragma unroll
        for (int kc = 0; kc < 8; kc++) {
            const uint32_t swz = (uint32_t)(((2 * kc + cp_) ^ sx) << 4);
            uint32_t qb4[16];
#pragma unroll
            for (int t = 0; t < 4; t++) ldmx4(&qb4[t * 4], qbase + t * 4096 + swz);
#pragma unroll
            for (int j = 0; j < 8; j++)
                mma16816(sc[j], kf[kc], &qb4[(j >> 1) * 4 + (j & 1) * 2]);
        }

        // ---- sigmoid -> P fragments (registers only) ----
        uint32_t p[8][2];
#pragma unroll
        for (int j = 0; j < 8; j++) {
            p[j][0] = packh2(sigf(sc[j][0]), sigf(sc[j][1]));
            p[j][1] = packh2(sigf(sc[j][2]), sigf(sc[j][3]));
        }

        // ---- MMA2: O[16 m, 128 v] += P . V^T ----
        const uint32_t vbase = sb + SM_V + buf * 16384 + rL * 128;
#pragma unroll
        for (int kc = 0; kc < 4; kc++) {
            const uint32_t swz = (uint32_t)(((2 * kc + cp_) ^ sx) << 4);
            uint32_t a[4] = { p[2 * kc][0], p[2 * kc][1], p[2 * kc + 1][0], p[2 * kc + 1][1] };
#pragma unroll
            for (int j = 0; j < 8; j++) {
                uint32_t vb[4];
                ldmx4(vb, vbase + j * 2048 + swz);
                mma16816(ob[2 * j],     a, &vb[0]);
                mma16816(ob[2 * j + 1], a, &vb[2]);
            }
        }

        CPA_WAIT0();
        __syncthreads();
    }

    // ---- epilogue: O'[m,v] -> O[b][v][m0+m] ----
    float* Ob = O + (size_t)b * D_ * N_ + m0;
    const int r  = w * 16 + (lane >> 2);
    const int c0 = 2 * (lane & 3);
#pragma unroll
    for (int i = 0; i < 16; i++) {
        const int v = 8 * i + c0;
        Ob[(size_t)v * N_ + r]           = ob[i][0];
        Ob[(size_t)(v + 1) * N_ + r]     = ob[i][1];
        Ob[(size_t)v * N_ + r + 8]       = ob[i][2];
        Ob[(size_t)(v + 1) * N_ + r + 8] = ob[i][3];
    }
}

// ---- preprocess: transpose Q,K -> [b][n][d] fp16; cast V -> fp16 ----
__global__ void prep_transpose(const float* __restrict__ Q, const float* __restrict__ K) {
    __shared__ float t[32][33];
    int which = blockIdx.z >> 3, b = blockIdx.z & 7;
    const float* src = (which ? K : Q) + (size_t)b * D_ * N_;
    __half* dst = (which ? g_Kt : g_Qt) + (size_t)b * N_ * D_;
    int n0 = blockIdx.x * 32, d0 = blockIdx.y * 32;
#pragma unroll
    for (int r = threadIdx.y; r < 32; r += 8)
        t[r][threadIdx.x] = src[(size_t)(d0 + r) * N_ + n0 + threadIdx.x];
    __syncthreads();
#pragma unroll
    for (int r = threadIdx.y; r < 32; r += 8)
        dst[(size_t)(n0 + r) * D_ + d0 + threadIdx.x] = __float2half(t[threadIdx.x][r]);
}
__global__ void prep_castV(const float* __restrict__ V) {
    int i = blockIdx.x * 256 + threadIdx.x;
    float4 v = ((const float4*)V)[i];
    __half2* o = (__half2*)g_Vh;
    o[2 * i]     = __floats2half2_rn(v.x, v.y);
    o[2 * i + 1] = __floats2half2_rn(v.z, v.w);
}

extern "C" void kernel_launch(void* const* d_in, const int* in_sizes, int n_in,
                              void* d_out, int out_size) {
    const float* Q = (const float*)d_in[0];
    const float* K = (const float*)d_in[1];
    const float* V = (const float*)d_in[2];
    float* O = (float*)d_out;

    prep_transpose<<<dim3(N_ / 32, D_ / 32, 16), dim3(32, 8)>>>(Q, K);
    prep_castV<<<(B_ * D_ * N_ / 4) / 256, 256>>>(V);

    cudaFuncSetAttribute(sigattn_hmma, cudaFuncAttributeMaxDynamicSharedMemorySize, SMEM_TOTAL);
    sigattn_hmma<<<dim3(N_ / 128, B_), 256, SMEM_TOTAL>>>(O);
}

// round 5
// speedup vs baseline: 9.2516x; 1.1794x over previous
#include <cuda_runtime.h>
#include <cuda_fp16.h>
#include <cstdint>

#define B_ 8
#define D_ 128
#define N_ 2048
#define BN 64
#define NITER (N_ / BN)

__device__ __align__(16) __half g_Qh[B_ * D_ * N_];  // [b][d][n] fp16 (native layout)
__device__ __align__(16) __half g_Kh[B_ * D_ * N_];  // [b][d][m]
__device__ __align__(16) __half g_Vh[B_ * D_ * N_];  // [b][v][n]

__device__ __forceinline__ uint32_t s2u(const void* p) {
    uint32_t a;
    asm("{ .reg .u64 t; cvta.to.shared.u64 t, %1; cvt.u32.u64 %0, t; }" : "=r"(a) : "l"(p));
    return a;
}

#define CPA16(dst, src) \
    asm volatile("cp.async.cg.shared.global [%0], [%1], 16;" :: "r"(dst), "l"(src))
#define CPA_COMMIT() asm volatile("cp.async.commit_group;" ::: "memory")
#define CPA_WAIT0()  asm volatile("cp.async.wait_group 0;" ::: "memory")

__device__ __forceinline__ void ldmx4(uint32_t* r, uint32_t addr) {
    asm volatile("ldmatrix.sync.aligned.m8n8.x4.shared.b16 {%0,%1,%2,%3}, [%4];"
        : "=r"(r[0]), "=r"(r[1]), "=r"(r[2]), "=r"(r[3]) : "r"(addr));
}
__device__ __forceinline__ void ldmx4t(uint32_t* r, uint32_t addr) {
    asm volatile("ldmatrix.sync.aligned.m8n8.x4.trans.shared.b16 {%0,%1,%2,%3}, [%4];"
        : "=r"(r[0]), "=r"(r[1]), "=r"(r[2]), "=r"(r[3]) : "r"(addr));
}
__device__ __forceinline__ void mma16816(float* d, const uint32_t* a, const uint32_t* b) {
    asm volatile("mma.sync.aligned.m16n8k16.row.col.f32.f16.f16.f32 "
        "{%0,%1,%2,%3}, {%4,%5,%6,%7}, {%8,%9}, {%0,%1,%2,%3};"
        : "+f"(d[0]), "+f"(d[1]), "+f"(d[2]), "+f"(d[3])
        : "r"(a[0]), "r"(a[1]), "r"(a[2]), "r"(a[3]), "r"(b[0]), "r"(b[1]));
}

// sigmoid(x/sqrt(128)) = 0.5*tanh(x/(2*sqrt(128))) + 0.5  (single MUFU)
__device__ __forceinline__ float sigf(float x) {
    const float c = 0.5f * 0.08838834764831845f;
    float t;
    asm("tanh.approx.f32 %0, %1;" : "=f"(t) : "f"(x * c));
    return fmaf(t, 0.5f, 0.5f);
}
__device__ __forceinline__ uint32_t packh2(float a, float b) {
    uint32_t r;
    asm("cvt.rn.f16x2.f32 %0, %1, %2;" : "=r"(r) : "f"(b), "f"(a));
    return r;
}

// smem: K [d=128][m=128] 32KB @0, Q[buf] [d=128][n=64] 16KB @32K, V[buf] [v=128][n=64] 16KB @64K
#define SM_K 0
#define SM_Q 32768
#define SM_V 65536
#define SMEM_TOTAL 98304

__global__ __launch_bounds__(256, 1)
void sigattn_hmma(float* __restrict__ O) {
    extern __shared__ char sm[];
    const uint32_t sb = s2u(sm);
    const int tid = threadIdx.x, w = tid >> 5, lane = tid & 31;
    const int b = blockIdx.y, m0 = blockIdx.x * 128;
    const int g = lane >> 3, sx = lane & 7;

    auto loadQV = [&](int it, int buf) {
        const int n0 = it * BN;
        const uint32_t qd = sb + SM_Q + buf * 16384;
        const uint32_t vd = sb + SM_V + buf * 16384;
#pragma unroll
        for (int r = 0; r < 4; r++) {
            int i = tid + r * 256;
            int d = i >> 3, c = i & 7;                 // 128 rows x 8 chunks(16B)
            uint32_t off = (uint32_t)(d * 128 + ((c ^ (d & 7)) << 4));
            CPA16(qd + off, (const char*)g_Qh + ((size_t)(b * D_ + d) * N_ + n0 + c * 8) * 2);
            CPA16(vd + off, (const char*)g_Vh + ((size_t)(b * D_ + d) * N_ + n0 + c * 8) * 2);
        }
    };

    // prologue: K tile [d][m0..m0+127] + (Q,V)(0)
#pragma unroll
    for (int r = 0; r < 8; r++) {
        int i = tid + r * 256;
        int d = i >> 4, c = i & 15;                    // 128 rows x 16 chunks
        CPA16(sb + SM_K + d * 256 + ((c ^ (d & 7)) << 4),
              (const char*)g_Kh + ((size_t)(b * D_ + d) * N_ + m0 + c * 8) * 2);
    }
    loadQV(0, 0);
    CPA_COMMIT();
    CPA_WAIT0();
    __syncthreads();

    // ---- K frags (A m16k16, m-block = w) via ldmatrix.trans from [d][m] ----
    uint32_t kf[8][4];
    {
        const int drow = (g >> 1) * 8 + sx;            // d offset within 16-chunk
        const uint32_t coff = (uint32_t)((((2 * w + (g & 1)) ^ sx) & 15) << 4);
#pragma unroll
        for (int kc = 0; kc < 8; kc++)
            ldmx4t(kf[kc], sb + SM_K + (uint32_t)((kc * 16 + drow) * 256) + coff);
    }

    float ob[16][4];
#pragma unroll
    for (int i = 0; i < 16; i++)
#pragma unroll
        for (int j = 0; j < 4; j++) ob[i][j] = 0.0f;

    const int qrow  = (g & 1) * 8 + sx;                // Q trans-tile d-row offset
    const int qcoff = g >> 1;                          // Q chunk parity
    const int rL    = sx + ((lane >> 4) << 3);         // V ldmatrix row
    const int cp_   = g & 1;                           // V chunk parity

    for (int it = 0; it < NITER; it++) {
        const int buf = it & 1;
        if (it + 1 < NITER) loadQV(it + 1, buf ^ 1);
        CPA_COMMIT();

        // ---- MMA1: S'[16m, 64n] = K . Q^T (Q frags via ldmatrix.trans) ----
        float sc[8][4];
#pragma unroll
        for (int j = 0; j < 8; j++)
#pragma unroll
            for (int q = 0; q < 4; q++) sc[j][q] = 0.0f;

        const uint32_t qbuf = sb + SM_Q + buf * 16384;
#pragma unroll
        for (int kc = 0; kc < 8; kc++) {
            uint32_t qb4[16];
            const uint32_t qr = qbuf + (uint32_t)((kc * 16 + qrow) * 128);
#pragma unroll
            for (int t = 0; t < 4; t++)
                ldmx4t(&qb4[t * 4], qr + (uint32_t)((((2 * t + qcoff) ^ sx) & 7) << 4));
#pragma unroll
            for (int j = 0; j < 8; j++)
                mma16816(sc[j], kf[kc], &qb4[(j >> 1) * 4 + (j & 1) * 2]);
        }

        // ---- sigmoid -> P frags (registers only) ----
        uint32_t p[8][2];
#pragma unroll
        for (int j = 0; j < 8; j++) {
            p[j][0] = packh2(sigf(sc[j][0]), sigf(sc[j][1]));
            p[j][1] = packh2(sigf(sc[j][2]), sigf(sc[j][3]));
        }

        // ---- MMA2: O[16m, 128v] += P . V^T ----
        const uint32_t vbase = sb + SM_V + buf * 16384 + (uint32_t)(rL * 128);
#pragma unroll
        for (int kc = 0; kc < 4; kc++) {
            const uint32_t swz = (uint32_t)((((2 * kc + cp_) ^ sx) & 7) << 4);
            uint32_t a[4] = { p[2 * kc][0], p[2 * kc][1], p[2 * kc + 1][0], p[2 * kc + 1][1] };
#pragma unroll
            for (int j = 0; j < 8; j++) {
                uint32_t vb[4];
                ldmx4(vb, vbase + (uint32_t)(j * 2048) + swz);
                mma16816(ob[2 * j],     a, &vb[0]);
                mma16816(ob[2 * j + 1], a, &vb[2]);
            }
        }

        CPA_WAIT0();
        __syncthreads();
    }

    // ---- epilogue: O'[m,v] -> O[b][v][m0+m] ----
    float* Ob = O + (size_t)b * D_ * N_ + m0;
    const int r  = w * 16 + (lane >> 2);
    const int c0 = 2 * (lane & 3);
#pragma unroll
    for (int i = 0; i < 16; i++) {
        const int v = 8 * i + c0;
        Ob[(size_t)v * N_ + r]           = ob[i][0];
        Ob[(size_t)(v + 1) * N_ + r]     = ob[i][1];
        Ob[(size_t)v * N_ + r + 8]       = ob[i][2];
        Ob[(size_t)(v + 1) * N_ + r + 8] = ob[i][3];
    }
}

// ---- preprocess: pure fp32 -> fp16 cast, native layouts ----
__global__ void prep_cast(const float* __restrict__ Q, const float* __restrict__ K,
                          const float* __restrict__ V) {
    int i = blockIdx.x * 256 + threadIdx.x;
    const float* src = (blockIdx.y == 0) ? Q : (blockIdx.y == 1) ? K : V;
    __half* dst = (blockIdx.y == 0) ? g_Qh : (blockIdx.y == 1) ? g_Kh : g_Vh;
    float4 v = ((const float4*)src)[i];
    __half2* o = (__half2*)dst;
    o[2 * i]     = __floats2half2_rn(v.x, v.y);
    o[2 * i + 1] = __floats2half2_rn(v.z, v.w);
}

extern "C" void kernel_launch(void* const* d_in, const int* in_sizes, int n_in,
                              void* d_out, int out_size) {
    const float* Q = (const float*)d_in[0];
    const float* K = (const float*)d_in[1];
    const float* V = (const float*)d_in[2];
    float* O = (float*)d_out;

    prep_cast<<<dim3((B_ * D_ * N_ / 4) / 256, 3), 256>>>(Q, K, V);

    cudaFuncSetAttribute(sigattn_hmma, cudaFuncAttributeMaxDynamicSharedMemorySize, SMEM_TOTAL);
    sigattn_hmma<<<dim3(N_ / 128, B_), 256, SMEM_TOTAL>>>(O);
}